// round 6
// baseline (speedup 1.0000x reference)
#include <cuda_runtime.h>
#include <cuda_fp16.h>

// Problem constants
#define NW 16384   // words
#define WL 16      // word length
#define D  300     // hidden dim
#define DP 320     // padded channel count (zeros in [300,320))
#define NL 128     // letters
#define KS 3       // conv taps

// Encode config: 4 uniform slices of 80 channels over the padded 320.
#define SU4 10                      // uint4 chunks per row per slice (80 ch)
#define NSL 4
#define BPS 111                     // blocks per slice (4*111 = 444 = 3*148)
#define WPB 16
#define ENC_THREADS 512
#define ENC_SMEM (KS * NL * SU4 * 16 + 80 * 4)   // 61440 + 320 = 61760 B -> 3 CTA/SM

// Device scratch
__device__ __half g_Ph[KS][NL][DP];  // per-letter conv partials (fp16, padded)
__device__ float  g_embT[D * NL];    // emb transposed: [i][v]
__device__ uint4  g_wpk[NW];         // packed letters: 16 u8 per word

// ---------------------------------------------------------------------------
// Kernel A (fused prep): blocks 0-39 transpose emb [128][300] -> embT
// [300][128]; blocks 40-103 pack each word's 16 letters into one uint4.
// ---------------------------------------------------------------------------
__global__ __launch_bounds__(256) void prep_kernel(const float* __restrict__ emb,
                                                   const int* __restrict__ words) {
    if (blockIdx.x < 40) {
        __shared__ float t[32][33];
        const int bx = blockIdx.x % 10, by = blockIdx.x / 10;
        const int i0 = bx * 32, v0 = by * 32;
        const int x = threadIdx.x & 31, y = threadIdx.x >> 5;  // 32 x 8
#pragma unroll
        for (int dy = 0; dy < 32; dy += 8) {
            int v = v0 + y + dy, i = i0 + x;
            t[y + dy][x] = (i < D) ? emb[v * D + i] : 0.f;
        }
        __syncthreads();
#pragma unroll
        for (int dy = 0; dy < 32; dy += 8) {
            int i = i0 + y + dy, v = v0 + x;
            if (i < D) g_embT[i * NL + v] = t[x][y + dy];
        }
    } else {
        const int n = (blockIdx.x - 40) * 256 + threadIdx.x;
        unsigned r0 = 0, r1 = 0, r2 = 0, r3 = 0;
#pragma unroll
        for (int l = 0; l < 4; ++l)  r0 |= ((unsigned)words[l * NW + n] & 0xFF) << (l * 8);
#pragma unroll
        for (int l = 4; l < 8; ++l)  r1 |= ((unsigned)words[l * NW + n] & 0xFF) << ((l - 4) * 8);
#pragma unroll
        for (int l = 8; l < 12; ++l) r2 |= ((unsigned)words[l * NW + n] & 0xFF) << ((l - 8) * 8);
#pragma unroll
        for (int l = 12; l < 16; ++l) r3 |= ((unsigned)words[l * NW + n] & 0xFF) << ((l - 12) * 8);
        g_wpk[n] = make_uint4(r0, r1, r2, r3);
    }
}

// ---------------------------------------------------------------------------
// Kernel B: build P. 107 blocks x 384 threads = (3 output channels) x (128
// letters). embT streamed once per block (3 groups L1-share it); w rows staged
// de-interleaved in smem. Zeros for padded channels o in [300,320).
// ---------------------------------------------------------------------------
__global__ __launch_bounds__(384) void compute_P_kernel(const float* __restrict__ w) {
    __shared__ __align__(16) float ws[3][KS][304];  // 10.9 KB
    const int j = threadIdx.x >> 7;   // 0..2
    const int v = threadIdx.x & 127;
    const int o = blockIdx.x * 3 + j;
    const int ob = blockIdx.x * 3;

    for (int t = threadIdx.x; t < 3 * D * KS; t += 384) {
        int jj = t / (D * KS), r = t % (D * KS);
        int oo = ob + jj;
        ws[jj][r % 3][r / 3] = (oo < D) ? w[oo * D * KS + r] : 0.f;
    }
    __syncthreads();

    if (o >= DP) return;
    float a0 = 0.f, a1 = 0.f, a2 = 0.f;
    if (o < D) {
        const float* et = g_embT + v;  // stride NL, coalesced across lanes
#pragma unroll 5
        for (int i = 0; i < D; i += 4) {
            float4 w0 = *(const float4*)&ws[j][0][i];
            float4 w1 = *(const float4*)&ws[j][1][i];
            float4 w2 = *(const float4*)&ws[j][2][i];
            float e0 = et[(i + 0) * NL];
            float e1 = et[(i + 1) * NL];
            float e2 = et[(i + 2) * NL];
            float e3 = et[(i + 3) * NL];
            a0 = fmaf(e0, w0.x, a0); a1 = fmaf(e0, w1.x, a1); a2 = fmaf(e0, w2.x, a2);
            a0 = fmaf(e1, w0.y, a0); a1 = fmaf(e1, w1.y, a1); a2 = fmaf(e1, w2.y, a2);
            a0 = fmaf(e2, w0.z, a0); a1 = fmaf(e2, w1.z, a1); a2 = fmaf(e2, w2.z, a2);
            a0 = fmaf(e3, w0.w, a0); a1 = fmaf(e3, w1.w, a1); a2 = fmaf(e3, w2.w, a2);
        }
    }
    g_Ph[0][v][o] = __float2half(a0);
    g_Ph[1][v][o] = __float2half(a1);
    g_Ph[2][v][o] = __float2half(a2);
}

// ---------------------------------------------------------------------------
// Kernel C: encode. 444 blocks (111 per 80-ch slice), 512 thr, 3 CTA/SM.
// Block stages its fp16 P-slice (60 KB) + bias slice in smem; each warp
// handles 2 words (half-warp each), letters via one broadcast LDG.128,
// prefetched. Per position: 3 conflict-free LDS.128 + half2 add/max.
// ---------------------------------------------------------------------------
#define GETL(l) ((lw[(l) >> 2] >> (((l) & 3) * 8)) & 0xFF)

__global__ __launch_bounds__(ENC_THREADS, 3) void encode_kernel(const float* __restrict__ bias,
                                                                float* __restrict__ out) {
    extern __shared__ uint4 Pv[];              // [KS*NL rows][SU4]
    float* bs = (float*)(Pv + KS * NL * SU4);  // 80 bias floats

    const int slice = blockIdx.x / BPS;
    const int lb    = blockIdx.x % BPS;
    const int c0    = slice * 80;

    const uint4* gP = (const uint4*)g_Ph;  // row stride DP/8 = 40 uint4
    for (int idx = threadIdx.x; idx < KS * NL * SU4; idx += ENC_THREADS) {
        int r = idx / SU4, c = idx % SU4;
        Pv[idx] = gP[r * (DP / 8) + slice * SU4 + c];
    }
    if (threadIdx.x < 80) {
        int ch = c0 + threadIdx.x;
        bs[threadIdx.x] = (ch < D) ? bias[ch] : 0.f;
    }
    __syncthreads();

    const int lane  = threadIdx.x & 31;
    const int lo    = lane & 15;
    const int half  = lane >> 4;
    const int wid   = threadIdx.x >> 5;
    const int wsl   = lb * WPB + wid;
    const int nwarp = BPS * WPB;

    const bool active = lo < SU4;
    const int ch = c0 + lo * 8;

    const __half NH = __ushort_as_half((unsigned short)0xFC00);  // -inf
    const half2 NEGI = __halves2half2(NH, NH);

    if (wsl >= NW / 2) return;
    uint4 pk = g_wpk[2 * wsl + half];

    for (int p = wsl; p < NW / 2; p += nwarp) {
        const int pn = p + nwarp;
        uint4 nxt = make_uint4(0, 0, 0, 0);
        if (pn < NW / 2) nxt = g_wpk[2 * pn + half];

        unsigned lw[4] = {pk.x, pk.y, pk.z, pk.w};
        const int gw = 2 * p + half;

        if (active) {
            half2 m0 = NEGI, m1 = NEGI, m2 = NEGI, m3 = NEGI;
#pragma unroll
            for (int l = 0; l < WL; ++l) {
                int ic = GETL(l) * SU4 + lo;
                uint4 a = Pv[NL * SU4 + ic];  // k=1, this char
                half2 h0 = *(half2*)&a.x, h1 = *(half2*)&a.y;
                half2 h2 = *(half2*)&a.z, h3 = *(half2*)&a.w;
                if (l > 0) {
                    uint4 q = Pv[GETL(l - 1) * SU4 + lo];  // k=0, prev char
                    h0 = __hadd2(h0, *(half2*)&q.x); h1 = __hadd2(h1, *(half2*)&q.y);
                    h2 = __hadd2(h2, *(half2*)&q.z); h3 = __hadd2(h3, *(half2*)&q.w);
                }
                if (l < WL - 1) {
                    uint4 q = Pv[2 * NL * SU4 + GETL(l + 1) * SU4 + lo];  // k=2
                    h0 = __hadd2(h0, *(half2*)&q.x); h1 = __hadd2(h1, *(half2*)&q.y);
                    h2 = __hadd2(h2, *(half2*)&q.z); h3 = __hadd2(h3, *(half2*)&q.w);
                }
                m0 = __hmax2(m0, h0); m1 = __hmax2(m1, h1);
                m2 = __hmax2(m2, h2); m3 = __hmax2(m3, h3);
            }

            float2 f0 = __half22float2(m0), f1 = __half22float2(m1);
            float2 f2 = __half22float2(m2), f3 = __half22float2(m3);
            float* op = out + (size_t)gw * D + ch;
            if (ch < D) {
                float4 bb = *(float4*)&bs[lo * 8];
                float4 r;
                r.x = fmaxf(f0.x + bb.x, 0.f); r.y = fmaxf(f0.y + bb.y, 0.f);
                r.z = fmaxf(f1.x + bb.z, 0.f); r.w = fmaxf(f1.y + bb.w, 0.f);
                *(float4*)op = r;
            }
            if (ch + 4 < D) {
                float4 bb = *(float4*)&bs[lo * 8 + 4];
                float4 r;
                r.x = fmaxf(f2.x + bb.x, 0.f); r.y = fmaxf(f2.y + bb.y, 0.f);
                r.z = fmaxf(f3.x + bb.z, 0.f); r.w = fmaxf(f3.y + bb.w, 0.f);
                *(float4*)(op + 4) = r;
            }
        }
        pk = nxt;
    }
}

// ---------------------------------------------------------------------------
// Launch. Inputs: words(int32), emb(f32), conv_w(f32), conv_b(f32). Out f32.
// ---------------------------------------------------------------------------
extern "C" void kernel_launch(void* const* d_in, const int* in_sizes, int n_in,
                              void* d_out, int out_size) {
    const int*   words = (const int*)d_in[0];
    const float* emb   = (const float*)d_in[1];
    const float* w     = (const float*)d_in[2];
    const float* b     = (const float*)d_in[3];
    float*       out   = (float*)d_out;

    prep_kernel<<<104, 256>>>(emb, words);
    compute_P_kernel<<<107, 384>>>(w);

    cudaFuncSetAttribute(encode_kernel,
                         cudaFuncAttributeMaxDynamicSharedMemorySize, ENC_SMEM);
    encode_kernel<<<NSL * BPS, ENC_THREADS, ENC_SMEM>>>(b, out);
}

// round 7
// speedup vs baseline: 1.0910x; 1.0910x over previous
#include <cuda_runtime.h>
#include <cuda_fp16.h>

// Problem constants
#define NW 16384   // words
#define WL 16      // word length
#define D  300     // hidden dim
#define DP 320     // padded channel count (zeros in [300,320))
#define NL 128     // letters
#define KS 3       // conv taps

// Encode config: 3 slices of 128/128/64 padded channels, balanced blocks.
#define WPB 16
#define ENC_THREADS 512
#define B0 99
#define B1 99
#define B2 98
#define ENC_BLOCKS (B0 + B1 + B2)           // 296 = 2 CTA/SM * 148 SMs
#define ENC_SMEM (KS * NL * 128 * 2)        // 96 KB -> 2 CTA/SM

// Device scratch
__device__ __half g_Ph[KS][NL][DP];  // per-letter conv partials (fp16, padded)
__device__ float  g_embT[D * NL];    // emb transposed: [i][v]
__device__ uint4  g_wpk[NW];         // packed letters: 16 u8 per word

// ---------------------------------------------------------------------------
// Kernel A (fused prep): blocks 0-39 transpose emb [128][300] -> embT
// [300][128]; blocks 40-103 pack each word's 16 letters into one uint4.
// ---------------------------------------------------------------------------
__global__ __launch_bounds__(256) void prep_kernel(const float* __restrict__ emb,
                                                   const int* __restrict__ words) {
    if (blockIdx.x < 40) {
        __shared__ float t[32][33];
        const int bx = blockIdx.x % 10, by = blockIdx.x / 10;
        const int i0 = bx * 32, v0 = by * 32;
        const int x = threadIdx.x & 31, y = threadIdx.x >> 5;  // 32 x 8
#pragma unroll
        for (int dy = 0; dy < 32; dy += 8) {
            int v = v0 + y + dy, i = i0 + x;
            t[y + dy][x] = (i < D) ? emb[v * D + i] : 0.f;
        }
        __syncthreads();
#pragma unroll
        for (int dy = 0; dy < 32; dy += 8) {
            int i = i0 + y + dy, v = v0 + x;
            if (i < D) g_embT[i * NL + v] = t[x][y + dy];
        }
    } else {
        const int n = (blockIdx.x - 40) * 256 + threadIdx.x;
        unsigned r0 = 0, r1 = 0, r2 = 0, r3 = 0;
#pragma unroll
        for (int l = 0; l < 4; ++l)  r0 |= ((unsigned)words[l * NW + n] & 0xFF) << (l * 8);
#pragma unroll
        for (int l = 4; l < 8; ++l)  r1 |= ((unsigned)words[l * NW + n] & 0xFF) << ((l - 4) * 8);
#pragma unroll
        for (int l = 8; l < 12; ++l) r2 |= ((unsigned)words[l * NW + n] & 0xFF) << ((l - 8) * 8);
#pragma unroll
        for (int l = 12; l < 16; ++l) r3 |= ((unsigned)words[l * NW + n] & 0xFF) << ((l - 12) * 8);
        g_wpk[n] = make_uint4(r0, r1, r2, r3);
    }
}

// ---------------------------------------------------------------------------
// Kernel B: build P. 107 blocks x 384 threads = (3 output channels) x (128
// letters). embT reads fully coalesced (lane = v); w rows staged
// de-interleaved in smem. Zeros for padded channels o in [300,320).
// ---------------------------------------------------------------------------
__global__ __launch_bounds__(384) void compute_P_kernel(const float* __restrict__ w) {
    __shared__ __align__(16) float ws[3][KS][304];  // 10.9 KB
    const int j = threadIdx.x >> 7;   // 0..2
    const int v = threadIdx.x & 127;
    const int o = blockIdx.x * 3 + j;
    const int ob = blockIdx.x * 3;

    for (int t = threadIdx.x; t < 3 * D * KS; t += 384) {
        int jj = t / (D * KS), r = t % (D * KS);
        int oo = ob + jj;
        ws[jj][r % 3][r / 3] = (oo < D) ? w[oo * D * KS + r] : 0.f;
    }
    __syncthreads();

    if (o >= DP) return;
    float a0 = 0.f, a1 = 0.f, a2 = 0.f;
    if (o < D) {
        const float* et = g_embT + v;  // stride NL, coalesced across lanes
#pragma unroll 5
        for (int i = 0; i < D; i += 4) {
            float4 w0 = *(const float4*)&ws[j][0][i];
            float4 w1 = *(const float4*)&ws[j][1][i];
            float4 w2 = *(const float4*)&ws[j][2][i];
            float e0 = et[(i + 0) * NL];
            float e1 = et[(i + 1) * NL];
            float e2 = et[(i + 2) * NL];
            float e3 = et[(i + 3) * NL];
            a0 = fmaf(e0, w0.x, a0); a1 = fmaf(e0, w1.x, a1); a2 = fmaf(e0, w2.x, a2);
            a0 = fmaf(e1, w0.y, a0); a1 = fmaf(e1, w1.y, a1); a2 = fmaf(e1, w2.y, a2);
            a0 = fmaf(e2, w0.z, a0); a1 = fmaf(e2, w1.z, a1); a2 = fmaf(e2, w2.z, a2);
            a0 = fmaf(e3, w0.w, a0); a1 = fmaf(e3, w1.w, a1); a2 = fmaf(e3, w2.w, a2);
        }
    }
    g_Ph[0][v][o] = __float2half(a0);
    g_Ph[1][v][o] = __float2half(a1);
    g_Ph[2][v][o] = __float2half(a2);
}

// ---------------------------------------------------------------------------
// Kernel C: encode. 296 blocks (99/99/98 per slice — BALANCED), 512 thr,
// 2 CTA/SM, exactly one wave. Block stages its fp16 P-slice (96 KB) in smem;
// each warp handles 2 words (half-warp each); letters via one broadcast
// LDG.128, prefetched one iteration ahead. Per position: 3 conflict-free
// LDS.128 + half2 adds + half2 running max. Bias + ReLU in fp32 at the end.
// ---------------------------------------------------------------------------
#define GETL(l) ((lw[(l) >> 2] >> (((l) & 3) * 8)) & 0xFF)

__global__ __launch_bounds__(ENC_THREADS, 2) void encode_kernel(const float* __restrict__ bias,
                                                                float* __restrict__ out) {
    extern __shared__ uint4 Pv[];  // [KS*NL rows][16 uint4]

    int b = blockIdx.x;
    int slice, lb, nb;
    if (b < B0)           { slice = 0; lb = b;           nb = B0; }
    else if (b < B0 + B1) { slice = 1; lb = b - B0;      nb = B1; }
    else                  { slice = 2; lb = b - B0 - B1; nb = B2; }
    const int c0 = slice * 128;
    const int nchunk = (slice == 2) ? 8 : 16;  // valid uint4 chunks per row

    const uint4* gP = (const uint4*)g_Ph;  // row stride DP/8 = 40 uint4
    for (int idx = threadIdx.x; idx < KS * NL * nchunk; idx += ENC_THREADS) {
        int r = idx / nchunk, c = idx % nchunk;
        Pv[r * 16 + c] = gP[r * (DP / 8) + slice * 16 + c];
    }
    __syncthreads();

    const int lane  = threadIdx.x & 31;
    const int lo    = lane & 15;
    const int half  = lane >> 4;   // 0 = word A, 1 = word B
    const int wid   = threadIdx.x >> 5;
    const int wsl   = lb * WPB + wid;
    const int nwarp = nb * WPB;

    const bool active = lo < nchunk;
    const int ch = c0 + lo * 8;

    float4 bb0 = make_float4(0.f, 0.f, 0.f, 0.f);
    float4 bb1 = bb0;
    if (active) {
        if (ch < D)     bb0 = *(const float4*)&bias[ch];
        if (ch + 4 < D) bb1 = *(const float4*)&bias[ch + 4];
    }

    const __half NH = __ushort_as_half((unsigned short)0xFC00);  // -inf
    const half2 NEGI = __halves2half2(NH, NH);

    uint4 pk = g_wpk[2 * wsl + half];  // prefetched letters for first word

    for (int p = wsl; p < NW / 2; p += nwarp) {
        const int pn = p + nwarp;
        uint4 nxt = make_uint4(0, 0, 0, 0);
        if (pn < NW / 2) nxt = g_wpk[2 * pn + half];

        unsigned lw[4] = {pk.x, pk.y, pk.z, pk.w};
        const int gw = 2 * p + half;

        if (active) {
            half2 m0 = NEGI, m1 = NEGI, m2 = NEGI, m3 = NEGI;
#pragma unroll
            for (int l = 0; l < WL; ++l) {
                uint4 a = Pv[(NL + GETL(l)) * 16 + lo];  // k=1, this char
                half2 h0 = *(half2*)&a.x, h1 = *(half2*)&a.y;
                half2 h2 = *(half2*)&a.z, h3 = *(half2*)&a.w;
                if (l > 0) {
                    uint4 q = Pv[GETL(l - 1) * 16 + lo];  // k=0, prev char
                    h0 = __hadd2(h0, *(half2*)&q.x); h1 = __hadd2(h1, *(half2*)&q.y);
                    h2 = __hadd2(h2, *(half2*)&q.z); h3 = __hadd2(h3, *(half2*)&q.w);
                }
                if (l < WL - 1) {
                    uint4 q = Pv[(2 * NL + GETL(l + 1)) * 16 + lo];  // k=2, next char
                    h0 = __hadd2(h0, *(half2*)&q.x); h1 = __hadd2(h1, *(half2*)&q.y);
                    h2 = __hadd2(h2, *(half2*)&q.z); h3 = __hadd2(h3, *(half2*)&q.w);
                }
                m0 = __hmax2(m0, h0); m1 = __hmax2(m1, h1);
                m2 = __hmax2(m2, h2); m3 = __hmax2(m3, h3);
            }

            float2 f0 = __half22float2(m0), f1 = __half22float2(m1);
            float2 f2 = __half22float2(m2), f3 = __half22float2(m3);
            float* op = out + (size_t)gw * D + ch;
            if (ch < D) {
                float4 r;
                r.x = fmaxf(f0.x + bb0.x, 0.f); r.y = fmaxf(f0.y + bb0.y, 0.f);
                r.z = fmaxf(f1.x + bb0.z, 0.f); r.w = fmaxf(f1.y + bb0.w, 0.f);
                *(float4*)op = r;
            }
            if (ch + 4 < D) {
                float4 r;
                r.x = fmaxf(f2.x + bb1.x, 0.f); r.y = fmaxf(f2.y + bb1.y, 0.f);
                r.z = fmaxf(f3.x + bb1.z, 0.f); r.w = fmaxf(f3.y + bb1.w, 0.f);
                *(float4*)(op + 4) = r;
            }
        }
        pk = nxt;
    }
}

// ---------------------------------------------------------------------------
// Launch. Inputs: words(int32), emb(f32), conv_w(f32), conv_b(f32). Out f32.
// ---------------------------------------------------------------------------
extern "C" void kernel_launch(void* const* d_in, const int* in_sizes, int n_in,
                              void* d_out, int out_size) {
    const int*   words = (const int*)d_in[0];
    const float* emb   = (const float*)d_in[1];
    const float* w     = (const float*)d_in[2];
    const float* b     = (const float*)d_in[3];
    float*       out   = (float*)d_out;

    prep_kernel<<<104, 256>>>(emb, words);
    compute_P_kernel<<<107, 384>>>(w);

    cudaFuncSetAttribute(encode_kernel,
                         cudaFuncAttributeMaxDynamicSharedMemorySize, ENC_SMEM);
    encode_kernel<<<ENC_BLOCKS, ENC_THREADS, ENC_SMEM>>>(b, out);
}

// round 8
// speedup vs baseline: 1.2876x; 1.1802x over previous
#include <cuda_runtime.h>
#include <cuda_fp16.h>

// Problem constants
#define NW 16384   // words
#define WL 16      // word length
#define D  300     // hidden dim
#define DP 320     // padded channel count (zeros in [300,320))
#define NL 128     // letters
#define KS 3       // conv taps

// Encode config: slices 0/1 = 128 ch (2 words/warp), slice 2 = 64 ch
// (4 words/warp, all lanes live). Blocks balanced by warp-iterations.
#define WPB 16
#define ENC_THREADS 512
#define B0 118
#define B1 118
#define B2 60
#define ENC_BLOCKS (B0 + B1 + B2)           // 296 = 2 CTA/SM * 148 SMs
#define ENC_SMEM (KS * NL * 128 * 2)        // 96 KB -> 2 CTA/SM

// Device scratch
__device__ __half g_Ph[KS][NL][DP];  // per-letter conv partials (fp16, padded)
__device__ float  g_embT[D * NL];    // emb transposed: [i][v]
__device__ uint4  g_wpk[NW];         // packed letters: 16 u8 per word

// ---------------------------------------------------------------------------
// Kernel A (fused prep): blocks 0-39 transpose emb [128][300] -> embT
// [300][128]; blocks 40-103 pack each word's 16 letters into one uint4.
// ---------------------------------------------------------------------------
__global__ __launch_bounds__(256) void prep_kernel(const float* __restrict__ emb,
                                                   const int* __restrict__ words) {
    if (blockIdx.x < 40) {
        __shared__ float t[32][33];
        const int bx = blockIdx.x % 10, by = blockIdx.x / 10;
        const int i0 = bx * 32, v0 = by * 32;
        const int x = threadIdx.x & 31, y = threadIdx.x >> 5;  // 32 x 8
#pragma unroll
        for (int dy = 0; dy < 32; dy += 8) {
            int v = v0 + y + dy, i = i0 + x;
            t[y + dy][x] = (i < D) ? emb[v * D + i] : 0.f;
        }
        __syncthreads();
#pragma unroll
        for (int dy = 0; dy < 32; dy += 8) {
            int i = i0 + y + dy, v = v0 + x;
            if (i < D) g_embT[i * NL + v] = t[x][y + dy];
        }
    } else {
        const int n = (blockIdx.x - 40) * 256 + threadIdx.x;
        unsigned r0 = 0, r1 = 0, r2 = 0, r3 = 0;
#pragma unroll
        for (int l = 0; l < 4; ++l)  r0 |= ((unsigned)words[l * NW + n] & 0xFF) << (l * 8);
#pragma unroll
        for (int l = 4; l < 8; ++l)  r1 |= ((unsigned)words[l * NW + n] & 0xFF) << ((l - 4) * 8);
#pragma unroll
        for (int l = 8; l < 12; ++l) r2 |= ((unsigned)words[l * NW + n] & 0xFF) << ((l - 8) * 8);
#pragma unroll
        for (int l = 12; l < 16; ++l) r3 |= ((unsigned)words[l * NW + n] & 0xFF) << ((l - 12) * 8);
        g_wpk[n] = make_uint4(r0, r1, r2, r3);
    }
}

// ---------------------------------------------------------------------------
// Kernel B: build P. 107 blocks x 384 threads = (3 output channels) x (128
// letters). embT reads fully coalesced (lane = v); w rows staged
// de-interleaved in smem. Zeros for padded channels o in [300,320).
// ---------------------------------------------------------------------------
__global__ __launch_bounds__(384) void compute_P_kernel(const float* __restrict__ w) {
    __shared__ __align__(16) float ws[3][KS][304];  // 10.9 KB
    const int j = threadIdx.x >> 7;   // 0..2
    const int v = threadIdx.x & 127;
    const int o = blockIdx.x * 3 + j;
    const int ob = blockIdx.x * 3;

    for (int t = threadIdx.x; t < 3 * D * KS; t += 384) {
        int jj = t / (D * KS), r = t % (D * KS);
        int oo = ob + jj;
        ws[jj][r % 3][r / 3] = (oo < D) ? w[oo * D * KS + r] : 0.f;
    }
    __syncthreads();

    if (o >= DP) return;
    float a0 = 0.f, a1 = 0.f, a2 = 0.f;
    if (o < D) {
        const float* et = g_embT + v;  // stride NL, coalesced across lanes
#pragma unroll 5
        for (int i = 0; i < D; i += 4) {
            float4 w0 = *(const float4*)&ws[j][0][i];
            float4 w1 = *(const float4*)&ws[j][1][i];
            float4 w2 = *(const float4*)&ws[j][2][i];
            float e0 = et[(i + 0) * NL];
            float e1 = et[(i + 1) * NL];
            float e2 = et[(i + 2) * NL];
            float e3 = et[(i + 3) * NL];
            a0 = fmaf(e0, w0.x, a0); a1 = fmaf(e0, w1.x, a1); a2 = fmaf(e0, w2.x, a2);
            a0 = fmaf(e1, w0.y, a0); a1 = fmaf(e1, w1.y, a1); a2 = fmaf(e1, w2.y, a2);
            a0 = fmaf(e2, w0.z, a0); a1 = fmaf(e2, w1.z, a1); a2 = fmaf(e2, w2.z, a2);
            a0 = fmaf(e3, w0.w, a0); a1 = fmaf(e3, w1.w, a1); a2 = fmaf(e3, w2.w, a2);
        }
    }
    g_Ph[0][v][o] = __float2half(a0);
    g_Ph[1][v][o] = __float2half(a1);
    g_Ph[2][v][o] = __float2half(a2);
}

// ---------------------------------------------------------------------------
// Kernel C: encode. 296 blocks (118/118/60), 512 thr, 2 CTA/SM, one wave.
// Slices 0/1 (128 ch): 2 words/warp. Slice 2 (64 ch): 4 words/warp so all
// 32 lanes stay live. Letters via one broadcast LDG.128, prefetched.
// ---------------------------------------------------------------------------
#define GETL(l) ((lw[(l) >> 2] >> (((l) & 3) * 8)) & 0xFF)

#define INNER_BODY(loidx)                                                        \
    half2 m0 = NEGI, m1 = NEGI, m2 = NEGI, m3 = NEGI;                            \
    _Pragma("unroll")                                                            \
    for (int l = 0; l < WL; ++l) {                                               \
        uint4 a = Pv[(NL + GETL(l)) * 16 + (loidx)];                             \
        half2 h0 = *(half2*)&a.x, h1 = *(half2*)&a.y;                            \
        half2 h2 = *(half2*)&a.z, h3 = *(half2*)&a.w;                            \
        if (l > 0) {                                                             \
            uint4 q = Pv[GETL(l - 1) * 16 + (loidx)];                            \
            h0 = __hadd2(h0, *(half2*)&q.x); h1 = __hadd2(h1, *(half2*)&q.y);    \
            h2 = __hadd2(h2, *(half2*)&q.z); h3 = __hadd2(h3, *(half2*)&q.w);    \
        }                                                                        \
        if (l < WL - 1) {                                                        \
            uint4 q = Pv[(2 * NL + GETL(l + 1)) * 16 + (loidx)];                 \
            h0 = __hadd2(h0, *(half2*)&q.x); h1 = __hadd2(h1, *(half2*)&q.y);    \
            h2 = __hadd2(h2, *(half2*)&q.z); h3 = __hadd2(h3, *(half2*)&q.w);    \
        }                                                                        \
        m0 = __hmax2(m0, h0); m1 = __hmax2(m1, h1);                              \
        m2 = __hmax2(m2, h2); m3 = __hmax2(m3, h3);                              \
    }

__global__ __launch_bounds__(ENC_THREADS, 2) void encode_kernel(const float* __restrict__ bias,
                                                                float* __restrict__ out) {
    extern __shared__ uint4 Pv[];  // [KS*NL rows][16 uint4]

    int b = blockIdx.x;
    int slice, lb, nb;
    if (b < B0)           { slice = 0; lb = b;           nb = B0; }
    else if (b < B0 + B1) { slice = 1; lb = b - B0;      nb = B1; }
    else                  { slice = 2; lb = b - B0 - B1; nb = B2; }
    const int c0 = slice * 128;
    const int nchunk = (slice == 2) ? 8 : 16;  // valid uint4 chunks per row

    const uint4* gP = (const uint4*)g_Ph;  // row stride DP/8 = 40 uint4
    for (int idx = threadIdx.x; idx < KS * NL * nchunk; idx += ENC_THREADS) {
        int r = idx / nchunk, c = idx % nchunk;
        Pv[r * 16 + c] = gP[r * (DP / 8) + slice * 16 + c];
    }
    __syncthreads();

    const int lane  = threadIdx.x & 31;
    const int wid   = threadIdx.x >> 5;
    const int wsl   = lb * WPB + wid;
    const int nwarp = nb * WPB;

    const __half NH = __ushort_as_half((unsigned short)0xFC00);  // -inf
    const half2 NEGI = __halves2half2(NH, NH);

    if (slice < 2) {
        // ---- 128-ch slice: 2 words per warp (16-lane halves) ----
        const int lo   = lane & 15;
        const int half = lane >> 4;
        const int ch   = c0 + lo * 8;

        float4 bb0 = *(const float4*)&bias[ch];
        float4 bb1 = *(const float4*)&bias[ch + 4];

        uint4 pk = g_wpk[2 * wsl + half];
        for (int p = wsl; p < NW / 2; p += nwarp) {
            const int pn = p + nwarp;
            uint4 nxt = make_uint4(0, 0, 0, 0);
            if (pn < NW / 2) nxt = g_wpk[2 * pn + half];

            unsigned lw[4] = {pk.x, pk.y, pk.z, pk.w};
            const int gw = 2 * p + half;

            INNER_BODY(lo)

            float2 f0 = __half22float2(m0), f1 = __half22float2(m1);
            float2 f2 = __half22float2(m2), f3 = __half22float2(m3);
            float* op = out + (size_t)gw * D + ch;
            float4 r;
            r.x = fmaxf(f0.x + bb0.x, 0.f); r.y = fmaxf(f0.y + bb0.y, 0.f);
            r.z = fmaxf(f1.x + bb0.z, 0.f); r.w = fmaxf(f1.y + bb0.w, 0.f);
            *(float4*)op = r;
            r.x = fmaxf(f2.x + bb1.x, 0.f); r.y = fmaxf(f2.y + bb1.y, 0.f);
            r.z = fmaxf(f3.x + bb1.z, 0.f); r.w = fmaxf(f3.y + bb1.w, 0.f);
            *(float4*)(op + 4) = r;

            pk = nxt;
        }
    } else {
        // ---- 64-ch slice (channels 256..299 real): 4 words per warp ----
        const int lo8 = lane & 7;
        const int g   = lane >> 3;
        const int ch  = c0 + lo8 * 8;  // 256..312

        float4 bb0 = make_float4(0.f, 0.f, 0.f, 0.f);
        float4 bb1 = bb0;
        if (ch < D)     bb0 = *(const float4*)&bias[ch];
        if (ch + 4 < D) bb1 = *(const float4*)&bias[ch + 4];

        uint4 pk = g_wpk[4 * wsl + g];
        for (int p = wsl; p < NW / 4; p += nwarp) {
            const int pn = p + nwarp;
            uint4 nxt = make_uint4(0, 0, 0, 0);
            if (pn < NW / 4) nxt = g_wpk[4 * pn + g];

            unsigned lw[4] = {pk.x, pk.y, pk.z, pk.w};
            const int gw = 4 * p + g;

            INNER_BODY(lo8)

            float2 f0 = __half22float2(m0), f1 = __half22float2(m1);
            float2 f2 = __half22float2(m2), f3 = __half22float2(m3);
            float* op = out + (size_t)gw * D + ch;
            if (ch < D) {
                float4 r;
                r.x = fmaxf(f0.x + bb0.x, 0.f); r.y = fmaxf(f0.y + bb0.y, 0.f);
                r.z = fmaxf(f1.x + bb0.z, 0.f); r.w = fmaxf(f1.y + bb0.w, 0.f);
                *(float4*)op = r;
            }
            if (ch + 4 < D) {
                float4 r;
                r.x = fmaxf(f2.x + bb1.x, 0.f); r.y = fmaxf(f2.y + bb1.y, 0.f);
                r.z = fmaxf(f3.x + bb1.z, 0.f); r.w = fmaxf(f3.y + bb1.w, 0.f);
                *(float4*)(op + 4) = r;
            }
            pk = nxt;
        }
    }
}

// ---------------------------------------------------------------------------
// Launch. Inputs: words(int32), emb(f32), conv_w(f32), conv_b(f32). Out f32.
// ---------------------------------------------------------------------------
extern "C" void kernel_launch(void* const* d_in, const int* in_sizes, int n_in,
                              void* d_out, int out_size) {
    const int*   words = (const int*)d_in[0];
    const float* emb   = (const float*)d_in[1];
    const float* w     = (const float*)d_in[2];
    const float* b     = (const float*)d_in[3];
    float*       out   = (float*)d_out;

    prep_kernel<<<104, 256>>>(emb, words);
    compute_P_kernel<<<107, 384>>>(w);

    cudaFuncSetAttribute(encode_kernel,
                         cudaFuncAttributeMaxDynamicSharedMemorySize, ENC_SMEM);
    encode_kernel<<<ENC_BLOCKS, ENC_THREADS, ENC_SMEM>>>(b, out);
}